// round 15
// baseline (speedup 1.0000x reference)
#include <cuda_runtime.h>
#include <cuda_fp16.h>
#include <cstdint>

static constexpr int E_   = 32;
static constexpr int H_   = 2048;
static constexpr int I_   = 768;
static constexpr int T_   = 2048;
static constexpr int MAXA = 8192;

// ---------------- scratch ----------------------------------------------------
__device__ int   g_counts[E_];
__device__ int   g_offsets[E_];
__device__ int   g_total;
__device__ int   g_tok[MAXA];
__device__ float g_w[MAXA];
__device__ int   g_inv[T_ * 4];
__device__ __align__(16) __half g_hs16[(size_t)T_ * H_];
__device__ __align__(16) __half g_act16[(size_t)MAXA * I_];
__device__ __align__(16) __half g_dout16[(size_t)MAXA * H_];

__device__ __forceinline__ uint32_t smem_u32(const void* p) {
    uint32_t a;
    asm("{ .reg .u64 t; cvta.to.shared.u64 t, %1; cvt.u32.u64 %0, t; }" : "=r"(a) : "l"(p));
    return a;
}
__device__ __forceinline__ void cpa16(uint32_t dst, const void* src) {
    asm volatile("cp.async.cg.shared.global [%0], [%1], 16;" :: "r"(dst), "l"(src));
}
__device__ __forceinline__ uint32_t pk2(float a, float b) {
    __half2 h = __floats2half2_rn(a, b);
    return *reinterpret_cast<uint32_t*>(&h);
}

// ---------------- fp32 -> fp16 streaming convert (hidden states only) ----------
__global__ void cvt_kernel(const float4* __restrict__ in, __half2* __restrict__ out, int n4) {
    for (int i = blockIdx.x * blockDim.x + threadIdx.x; i < n4;
         i += gridDim.x * blockDim.x) {
        float4 v = in[i];
        out[2 * i]     = __floats2half2_rn(v.x, v.y);
        out[2 * i + 1] = __floats2half2_rn(v.z, v.w);
    }
}

// ---------------- routing (known-good, R13) -------------------------------------
__global__ void route_kernel(const int* __restrict__ ridx,
                             const float* __restrict__ rw) {
    __shared__ int s_cnt[E_], s_cur[E_], s_off[E_];
    int tid = threadIdx.x;
    if (tid < E_) { s_cnt[tid] = 0; s_cur[tid] = 0; }
    __syncthreads();
    for (int t = tid; t < T_; t += blockDim.x) {
        int e0 = ridx[4*t], e1 = ridx[4*t+1], e2 = ridx[4*t+2], e3 = ridx[4*t+3];
        if (e0 != e1 && e0 != e2 && e0 != e3) atomicAdd(&s_cnt[e0], 1);
        if (e1 != e2 && e1 != e3)             atomicAdd(&s_cnt[e1], 1);
        if (e2 != e3)                          atomicAdd(&s_cnt[e2], 1);
        atomicAdd(&s_cnt[e3], 1);
    }
    __syncthreads();
    if (tid == 0) {
        int acc = 0;
        for (int e = 0; e < E_; e++) {
            s_off[e] = acc; g_offsets[e] = acc; g_counts[e] = s_cnt[e];
            acc += s_cnt[e];
        }
        g_total = acc;
    }
    __syncthreads();
    for (int t = tid; t < T_; t += blockDim.x) {
        int ee[4]; float ww[4];
        #pragma unroll
        for (int k = 0; k < 4; k++) { ee[k] = ridx[4*t+k]; ww[k] = rw[4*t+k]; }
        #pragma unroll
        for (int k = 0; k < 4; k++) {
            bool keep = true;
            #pragma unroll
            for (int j = k + 1; j < 4; j++) if (ee[j] == ee[k]) keep = false;
            int pos = -1;
            if (keep) {
                pos = s_off[ee[k]] + atomicAdd(&s_cur[ee[k]], 1);
                g_tok[pos] = t; g_w[pos] = ww[k];
            }
            g_inv[4*t + k] = pos;
        }
    }
}

// ---------------- fp16 grouped GEMM, fp32 B converted in-kernel (R13 core) -----
// 128x256 tile, 8 warps 64x64, k-chunk 32. A: cp.async fp16 4-stage.
// B: LDG fp32 -> cvt -> STS fp16, double-buffered. eBase = expert offset.
static constexpr int A_PITCH = 80;
static constexpr int A_STG   = 128 * A_PITCH;        // 10240
static constexpr int A_TOTAL = 4 * A_STG;            // 40960
static constexpr int B_PITCH = 528;
static constexpr int B_BUF   = 32 * B_PITCH;         // 16896
static constexpr int SMEM_BYTES = A_TOTAL + 2 * B_BUF;  // 74752

template<int KDIM, bool FIRST>
__global__ void __launch_bounds__(256, 1)
moe_gemm(const __half* __restrict__ Ain, const float* __restrict__ Bfp32, int eBase) {
    constexpr int NCH    = KDIM / 32;
    constexpr int LDB    = FIRST ? 1536 : 2048;
    constexpr int ROWSPE = FIRST ? 2048 : 768;
    constexpr int NOUT   = FIRST ? 128 : 256;

    extern __shared__ uint8_t smraw[];
    const int e   = eBase + blockIdx.z;
    const int cnt = g_counts[e];
    const int m0  = blockIdx.x * 128;
    if (m0 >= cnt) return;
    const int off = g_offsets[e];
    const int n0  = blockIdx.y * NOUT;
    const int tid = threadIdx.x;
    const int wid = tid >> 5, lane = tid & 31;
    const uint32_t sbase = smem_u32(smraw);

    // ---- A staging: row = tid>>1 (0..127), seg = tid&1 (32 B each) ----
    const int a_r = tid >> 1;
    const int a_s = tid & 1;
    int gmA = m0 + a_r;
    int rrA = (gmA < cnt) ? gmA : 0;
    const __half* aSrc = (FIRST ? Ain + (size_t)g_tok[off + rrA] * KDIM
                                : g_act16 + (size_t)(off + rrA) * KDIM) + a_s * 16;
    const uint32_t aDst = sbase + (uint32_t)(a_r * A_PITCH + a_s * 32);

    // ---- B staging: row = tid>>3 (0..31), seg s = tid&7 ----
    const int b_r = tid >> 3;
    const int b_s = tid & 7;
    const float* bColBase[4];
    #pragma unroll
    for (int j = 0; j < 4; j++) {
        int c8 = 8 * b_s + 64 * j;
        int gc = FIRST ? (c8 < 128 ? n0 + c8 : 768 + n0 + (c8 - 128))
                       : n0 + c8;
        bColBase[j] = Bfp32 + ((size_t)e * ROWSPE + b_r) * LDB + gc;
    }
    const uint32_t bDstBase = sbase + A_TOTAL + (uint32_t)(b_r * B_PITCH + b_s * 16);

    float4 breg[8];
    auto ldg_b = [&](int c) {
        const size_t roff = (size_t)c * 32 * LDB;
        #pragma unroll
        for (int j = 0; j < 4; j++) {
            breg[2 * j]     = *(const float4*)(bColBase[j] + roff);
            breg[2 * j + 1] = *(const float4*)(bColBase[j] + roff + 4);
        }
    };
    auto sts_b = [&](int c) {
        uint32_t dst = bDstBase + (uint32_t)(c & 1) * B_BUF;
        #pragma unroll
        for (int j = 0; j < 4; j++) {
            uint32_t h0 = pk2(breg[2*j].x,   breg[2*j].y);
            uint32_t h1 = pk2(breg[2*j].z,   breg[2*j].w);
            uint32_t h2 = pk2(breg[2*j+1].x, breg[2*j+1].y);
            uint32_t h3 = pk2(breg[2*j+1].z, breg[2*j+1].w);
            asm volatile("st.shared.v4.b32 [%0], {%1,%2,%3,%4};"
                         :: "r"(dst + (uint32_t)(j * 128)),
                            "r"(h0), "r"(h1), "r"(h2), "r"(h3) : "memory");
        }
    };
    auto cp_a = [&](int c) {
        const uint32_t so = (uint32_t)(c & 3) * A_STG;
        const __half* src = aSrc + (size_t)c * 32;
        cpa16(aDst + so, src);
        cpa16(aDst + so + 16, src + 8);
        asm volatile("cp.async.commit_group;" ::: "memory");
    };

    float acc[4][8][4];
    #pragma unroll
    for (int i = 0; i < 4; i++)
        #pragma unroll
        for (int j = 0; j < 8; j++)
            #pragma unroll
            for (int k = 0; k < 4; k++) acc[i][j][k] = 0.f;

    const int wm = (wid >> 2) * 64;
    const int wn = (wid & 3) * (FIRST ? 32 : 64);
    const int qr = lane >> 2;
    const int qk = lane & 3;

    const uint32_t a_lm_off = (uint32_t)((wm + (lane & 15)) * A_PITCH + (lane >> 4) * 16);
    const uint32_t b_lm_krow = (uint32_t)((lane & 7) + ((lane >> 3) & 1) * 8);
    const uint32_t b_lm_noff = (uint32_t)((lane >> 4) * 8 * 2);

    // ---- prologue ----
    ldg_b(0);
    cp_a(0); cp_a(1); cp_a(2);
    sts_b(0);
    ldg_b(1);

    for (int c = 0; c < NCH; c++) {
        int rem = NCH - 1 - c;
        if (rem >= 2)      asm volatile("cp.async.wait_group 2;" ::: "memory");
        else if (rem == 1) asm volatile("cp.async.wait_group 1;" ::: "memory");
        else               asm volatile("cp.async.wait_group 0;" ::: "memory");
        __syncthreads();
        if (c + 3 < NCH) cp_a(c + 3);

        const uint32_t sA = sbase + (uint32_t)(c & 3) * A_STG;
        const uint32_t sB = sbase + A_TOTAL + (uint32_t)(c & 1) * B_BUF;
        #pragma unroll
        for (int kk = 0; kk < 32; kk += 16) {
            uint32_t af[4][4], bf[8][2];
            #pragma unroll
            for (int mi = 0; mi < 4; mi++) {
                uint32_t addr = sA + a_lm_off + (uint32_t)(mi * 16 * A_PITCH + kk * 2);
                asm volatile(
                    "ldmatrix.sync.aligned.m8n8.x4.shared.b16 {%0,%1,%2,%3}, [%4];"
                    : "=r"(af[mi][0]), "=r"(af[mi][1]),
                      "=r"(af[mi][2]), "=r"(af[mi][3])
                    : "r"(addr));
            }
            #pragma unroll
            for (int nip = 0; nip < 4; nip++) {
                int ni = 2 * nip;
                int nb = FIRST ? (ni < 4 ? wn + ni * 8 : 128 + wn + (ni - 4) * 8)
                               : wn + ni * 8;
                uint32_t addr = sB + (kk + b_lm_krow) * B_PITCH
                                   + (uint32_t)(nb * 2) + b_lm_noff;
                asm volatile(
                    "ldmatrix.sync.aligned.m8n8.x4.trans.shared.b16 {%0,%1,%2,%3}, [%4];"
                    : "=r"(bf[ni][0]), "=r"(bf[ni][1]),
                      "=r"(bf[ni + 1][0]), "=r"(bf[ni + 1][1])
                    : "r"(addr));
            }
            #pragma unroll
            for (int mi = 0; mi < 4; mi++)
                #pragma unroll
                for (int ni = 0; ni < 8; ni++)
                    asm volatile(
                        "mma.sync.aligned.m16n8k16.row.col.f32.f16.f16.f32 "
                        "{%0,%1,%2,%3}, {%4,%5,%6,%7}, {%8,%9}, {%0,%1,%2,%3};"
                        : "+f"(acc[mi][ni][0]), "+f"(acc[mi][ni][1]),
                          "+f"(acc[mi][ni][2]), "+f"(acc[mi][ni][3])
                        : "r"(af[mi][0]), "r"(af[mi][1]),
                          "r"(af[mi][2]), "r"(af[mi][3]),
                          "r"(bf[ni][0]), "r"(bf[ni][1]));
        }
        if (c + 1 < NCH) {
            sts_b(c + 1);
            if (c + 2 < NCH) ldg_b(c + 2);
        }
    }
    __syncthreads();

    // ---- epilogue ----
    #pragma unroll
    for (int mi = 0; mi < 4; mi++) {
        #pragma unroll
        for (int half = 0; half < 2; half++) {
            int r  = wm + mi * 16 + qr + half * 8;
            int gm = m0 + r;
            if (gm >= cnt) continue;
            if (FIRST) {
                __half* rowp = g_act16 + (size_t)(off + gm) * I_ + n0;
                #pragma unroll
                for (int ni = 0; ni < 4; ni++) {
                    int nc = wn + ni * 8 + qk * 2;
                    float g0 = acc[mi][ni][half * 2 + 0];
                    float g1 = acc[mi][ni][half * 2 + 1];
                    float u0 = acc[mi][ni + 4][half * 2 + 0];
                    float u1 = acc[mi][ni + 4][half * 2 + 1];
                    float v0 = u0 * (g0 / (1.f + __expf(-g0)));
                    float v1 = u1 * (g1 / (1.f + __expf(-g1)));
                    *(__half2*)(rowp + nc) = __floats2half2_rn(v0, v1);
                }
            } else {
                float w = g_w[off + gm];
                __half* rowp = g_dout16 + (size_t)(off + gm) * H_ + n0;
                #pragma unroll
                for (int ni = 0; ni < 8; ni++) {
                    int nc = wn + ni * 8 + qk * 2;
                    *(__half2*)(rowp + nc) =
                        __floats2half2_rn(acc[mi][ni][half * 2 + 0] * w,
                                          acc[mi][ni][half * 2 + 1] * w);
                }
            }
        }
    }
}

// ---------------- combine: fp16 dout -> fp32 out --------------------------------
__global__ void combine_kernel(float4* __restrict__ out) {
    int idx = blockIdx.x * blockDim.x + threadIdx.x;
    if (idx >= T_ * H_ / 4) return;
    int t  = idx >> 9;
    int h4 = idx & 511;
    float4 s = make_float4(0.f, 0.f, 0.f, 0.f);
    #pragma unroll
    for (int k = 0; k < 4; k++) {
        int pos = g_inv[4 * t + k];
        if (pos >= 0) {
            const __half2* p = (const __half2*)(g_dout16 + (size_t)pos * H_ + h4 * 4);
            float2 a = __half22float2(p[0]);
            float2 b = __half22float2(p[1]);
            s.x += a.x; s.y += a.y; s.z += b.x; s.w += b.y;
        }
    }
    out[idx] = s;
}

// ---------------- launch --------------------------------------------------------
extern "C" void kernel_launch(void* const* d_in, const int* in_sizes, int n_in,
                              void* d_out, int out_size) {
    const float* hs  = (const float*)d_in[0];
    const float* rw  = (const float*)d_in[1];
    const int*   ri  = (const int*)d_in[2];
    const float* gup = (const float*)d_in[4];
    const float* dn  = (const float*)d_in[5];
    float* out = (float*)d_out;

    // one-time host resources (created outside capture on the correctness call)
    static cudaStream_t s2 = nullptr;
    static cudaEvent_t evA = nullptr, ev2A = nullptr;
    if (!s2) {
        cudaStreamCreateWithFlags(&s2, cudaStreamNonBlocking);
        cudaEventCreateWithFlags(&evA, cudaEventDisableTiming);
        cudaEventCreateWithFlags(&ev2A, cudaEventDisableTiming);
    }

    cudaFuncSetAttribute((const void*)moe_gemm<2048, true>,
                         cudaFuncAttributeMaxDynamicSharedMemorySize, SMEM_BYTES);
    cudaFuncSetAttribute((const void*)moe_gemm<768, false>,
                         cudaFuncAttributeMaxDynamicSharedMemorySize, SMEM_BYTES);

    __half2* hs16; cudaGetSymbolAddress((void**)&hs16, g_hs16);
    const __half* hs16c = (const __half*)hs16;

    route_kernel<<<1, 256>>>(ri, rw);
    cvt_kernel<<<1024, 256>>>((const float4*)hs, hs16, T_ * H_ / 4);

    // GEMM1 first half (experts 0-15)
    moe_gemm<2048, true><<<dim3(8, 6, 16), 256, SMEM_BYTES>>>(hs16c, gup, 0);
    cudaEventRecord(evA, 0);

    // fork: GEMM2 first half on s2, overlapping GEMM1 second half
    cudaStreamWaitEvent(s2, evA, 0);
    moe_gemm<768, false><<<dim3(8, 8, 16), 256, SMEM_BYTES, s2>>>(nullptr, dn, 0);
    cudaEventRecord(ev2A, s2);

    // GEMM1 second half (experts 16-31) on main, concurrent with G2a
    moe_gemm<2048, true><<<dim3(8, 6, 16), 256, SMEM_BYTES>>>(hs16c, gup, 16);

    // GEMM2 second half on main (after G1b in-order)
    moe_gemm<768, false><<<dim3(8, 8, 16), 256, SMEM_BYTES>>>(nullptr, dn, 16);

    // join: combine needs G2a (s2) and G2b (main)
    cudaStreamWaitEvent(0, ev2A, 0);
    combine_kernel<<<(T_ * H_ / 4 + 255) / 256, 256>>>((float4*)out);
}

// round 16
// speedup vs baseline: 1.0479x; 1.0479x over previous
#include <cuda_runtime.h>
#include <cuda_fp16.h>
#include <cstdint>

static constexpr int E_   = 32;
static constexpr int H_   = 2048;
static constexpr int I_   = 768;
static constexpr int T_   = 2048;
static constexpr int MAXA = 8192;

// ---------------- scratch ----------------------------------------------------
__device__ int   g_counts[E_];
__device__ int   g_offsets[E_];
__device__ int   g_total;
__device__ int   g_tok[MAXA];
__device__ float g_w[MAXA];
__device__ int   g_inv[T_ * 4];
__device__ __align__(16) __half g_hs16[(size_t)T_ * H_];
__device__ __align__(16) __half g_act16[(size_t)MAXA * I_];
__device__ __align__(16) __half g_dout16[(size_t)MAXA * H_];

__device__ __forceinline__ uint32_t smem_u32(const void* p) {
    uint32_t a;
    asm("{ .reg .u64 t; cvta.to.shared.u64 t, %1; cvt.u32.u64 %0, t; }" : "=r"(a) : "l"(p));
    return a;
}
__device__ __forceinline__ void cpa16(uint32_t dst, const void* src) {
    asm volatile("cp.async.cg.shared.global [%0], [%1], 16;" :: "r"(dst), "l"(src));
}
__device__ __forceinline__ uint32_t pk2(float a, float b) {
    __half2 h = __floats2half2_rn(a, b);
    return *reinterpret_cast<uint32_t*>(&h);
}

// ---------------- fp32 -> fp16 streaming convert (hidden states only) ----------
__global__ void cvt_kernel(const float4* __restrict__ in, __half2* __restrict__ out, int n4) {
    for (int i = blockIdx.x * blockDim.x + threadIdx.x; i < n4;
         i += gridDim.x * blockDim.x) {
        float4 v = in[i];
        out[2 * i]     = __floats2half2_rn(v.x, v.y);
        out[2 * i + 1] = __floats2half2_rn(v.z, v.w);
    }
}

// ---------------- routing (known-good) ------------------------------------------
__global__ void route_kernel(const int* __restrict__ ridx,
                             const float* __restrict__ rw) {
    __shared__ int s_cnt[E_], s_cur[E_], s_off[E_];
    int tid = threadIdx.x;
    if (tid < E_) { s_cnt[tid] = 0; s_cur[tid] = 0; }
    __syncthreads();
    for (int t = tid; t < T_; t += blockDim.x) {
        int e0 = ridx[4*t], e1 = ridx[4*t+1], e2 = ridx[4*t+2], e3 = ridx[4*t+3];
        if (e0 != e1 && e0 != e2 && e0 != e3) atomicAdd(&s_cnt[e0], 1);
        if (e1 != e2 && e1 != e3)             atomicAdd(&s_cnt[e1], 1);
        if (e2 != e3)                          atomicAdd(&s_cnt[e2], 1);
        atomicAdd(&s_cnt[e3], 1);
    }
    __syncthreads();
    if (tid == 0) {
        int acc = 0;
        for (int e = 0; e < E_; e++) {
            s_off[e] = acc; g_offsets[e] = acc; g_counts[e] = s_cnt[e];
            acc += s_cnt[e];
        }
        g_total = acc;
    }
    __syncthreads();
    for (int t = tid; t < T_; t += blockDim.x) {
        int ee[4]; float ww[4];
        #pragma unroll
        for (int k = 0; k < 4; k++) { ee[k] = ridx[4*t+k]; ww[k] = rw[4*t+k]; }
        #pragma unroll
        for (int k = 0; k < 4; k++) {
            bool keep = true;
            #pragma unroll
            for (int j = k + 1; j < 4; j++) if (ee[j] == ee[k]) keep = false;
            int pos = -1;
            if (keep) {
                pos = s_off[ee[k]] + atomicAdd(&s_cur[ee[k]], 1);
                g_tok[pos] = t; g_w[pos] = ww[k];
            }
            g_inv[4*t + k] = pos;
        }
    }
}

// ---------------- fp16 grouped GEMM: 128x128 tile, 8 warps 64x32, 2 CTAs/SM ----
// A: cp.async fp16 4-stage. B: LDG fp32 -> cvt -> STS fp16, double-buffered.
// FIRST: B smem = gate[0:64)|up[64:128); epilogue SwiGLU -> g_act16 (64 cols/tile)
// else : B smem = 128 n-cols; epilogue *w -> g_dout16
static constexpr int A_PITCH = 80;
static constexpr int A_STG   = 128 * A_PITCH;        // 10240
static constexpr int A_TOTAL = 4 * A_STG;            // 40960
static constexpr int B_PITCH = 272;                  // 128 fp16 = 256 B + 16 pad
static constexpr int B_BUF   = 32 * B_PITCH;         // 8704
static constexpr int SMEM_BYTES = A_TOTAL + 2 * B_BUF;  // 58368 (x2 CTAs = 116736)

template<int KDIM, bool FIRST>
__global__ void __launch_bounds__(256, 2)
moe_gemm(const __half* __restrict__ Ain, const float* __restrict__ Bfp32) {
    constexpr int NCH    = KDIM / 32;
    constexpr int LDB    = FIRST ? 1536 : 2048;
    constexpr int ROWSPE = FIRST ? 2048 : 768;
    constexpr int NOUT   = FIRST ? 64 : 128;         // output cols per tile

    extern __shared__ uint8_t smraw[];
    const int e   = blockIdx.z;
    const int cnt = g_counts[e];
    const int m0  = blockIdx.x * 128;   // m fastest
    if (m0 >= cnt) return;
    const int off = g_offsets[e];
    const int n0  = blockIdx.y * NOUT;
    const int tid = threadIdx.x;
    const int wid = tid >> 5, lane = tid & 31;
    const uint32_t sbase = smem_u32(smraw);

    // ---- A staging: row = tid>>1 (0..127), seg = tid&1 (32 B each) ----
    const int a_r = tid >> 1;
    const int a_s = tid & 1;
    int gmA = m0 + a_r;
    int rrA = (gmA < cnt) ? gmA : 0;
    const __half* aSrc = (FIRST ? Ain + (size_t)g_tok[off + rrA] * KDIM
                                : g_act16 + (size_t)(off + rrA) * KDIM) + a_s * 16;
    const uint32_t aDst = sbase + (uint32_t)(a_r * A_PITCH + a_s * 32);

    // ---- B staging: row = tid>>3 (0..31), seg s = tid&7; 2 col groups of 8 ----
    const int b_r = tid >> 3;
    const int b_s = tid & 7;
    const float* bColBase[2];
    #pragma unroll
    for (int j = 0; j < 2; j++) {
        int c8 = 8 * b_s + 64 * j;                   // fp16 col within 128
        int gc = FIRST ? (c8 < 64 ? n0 + c8 : 768 + n0 + (c8 - 64))
                       : n0 + c8;
        bColBase[j] = Bfp32 + ((size_t)e * ROWSPE + b_r) * LDB + gc;
    }
    const uint32_t bDstBase = sbase + A_TOTAL + (uint32_t)(b_r * B_PITCH + b_s * 16);

    float4 breg[4];
    auto ldg_b = [&](int c) {
        const size_t roff = (size_t)c * 32 * LDB;
        #pragma unroll
        for (int j = 0; j < 2; j++) {
            breg[2 * j]     = *(const float4*)(bColBase[j] + roff);
            breg[2 * j + 1] = *(const float4*)(bColBase[j] + roff + 4);
        }
    };
    auto sts_b = [&](int c) {
        uint32_t dst = bDstBase + (uint32_t)(c & 1) * B_BUF;
        #pragma unroll
        for (int j = 0; j < 2; j++) {
            uint32_t h0 = pk2(breg[2*j].x,   breg[2*j].y);
            uint32_t h1 = pk2(breg[2*j].z,   breg[2*j].w);
            uint32_t h2 = pk2(breg[2*j+1].x, breg[2*j+1].y);
            uint32_t h3 = pk2(breg[2*j+1].z, breg[2*j+1].w);
            asm volatile("st.shared.v4.b32 [%0], {%1,%2,%3,%4};"
                         :: "r"(dst + (uint32_t)(j * 128)),
                            "r"(h0), "r"(h1), "r"(h2), "r"(h3) : "memory");
        }
    };
    auto cp_a = [&](int c) {
        const uint32_t so = (uint32_t)(c & 3) * A_STG;
        const __half* src = aSrc + (size_t)c * 32;
        cpa16(aDst + so, src);
        cpa16(aDst + so + 16, src + 8);
        asm volatile("cp.async.commit_group;" ::: "memory");
    };

    float acc[4][4][4];
    #pragma unroll
    for (int i = 0; i < 4; i++)
        #pragma unroll
        for (int j = 0; j < 4; j++)
            #pragma unroll
            for (int k = 0; k < 4; k++) acc[i][j][k] = 0.f;

    const int wm = (wid >> 2) * 64;                  // 0 / 64
    const int wn = (wid & 3) * (FIRST ? 16 : 32);    // n block within acc layout
    const int qr = lane >> 2;
    const int qk = lane & 3;

    const uint32_t a_lm_off = (uint32_t)((wm + (lane & 15)) * A_PITCH + (lane >> 4) * 16);
    const uint32_t b_lm_krow = (uint32_t)((lane & 7) + ((lane >> 3) & 1) * 8);
    const uint32_t b_lm_noff = (uint32_t)((lane >> 4) * 8 * 2);

    // ---- prologue ----
    ldg_b(0);
    cp_a(0); cp_a(1); cp_a(2);
    sts_b(0);
    ldg_b(1);

    for (int c = 0; c < NCH; c++) {
        int rem = NCH - 1 - c;
        if (rem >= 2)      asm volatile("cp.async.wait_group 2;" ::: "memory");
        else if (rem == 1) asm volatile("cp.async.wait_group 1;" ::: "memory");
        else               asm volatile("cp.async.wait_group 0;" ::: "memory");
        __syncthreads();
        if (c + 3 < NCH) cp_a(c + 3);

        const uint32_t sA = sbase + (uint32_t)(c & 3) * A_STG;
        const uint32_t sB = sbase + A_TOTAL + (uint32_t)(c & 1) * B_BUF;
        #pragma unroll
        for (int kk = 0; kk < 32; kk += 16) {
            uint32_t af[4][4], bf[4][2];
            #pragma unroll
            for (int mi = 0; mi < 4; mi++) {
                uint32_t addr = sA + a_lm_off + (uint32_t)(mi * 16 * A_PITCH + kk * 2);
                asm volatile(
                    "ldmatrix.sync.aligned.m8n8.x4.shared.b16 {%0,%1,%2,%3}, [%4];"
                    : "=r"(af[mi][0]), "=r"(af[mi][1]),
                      "=r"(af[mi][2]), "=r"(af[mi][3])
                    : "r"(addr));
            }
            #pragma unroll
            for (int nip = 0; nip < 2; nip++) {
                int ni = 2 * nip;
                int nb = FIRST ? (ni < 2 ? wn + ni * 8 : 64 + wn + (ni - 2) * 8)
                               : wn + ni * 8;
                uint32_t addr = sB + (kk + b_lm_krow) * B_PITCH
                                   + (uint32_t)(nb * 2) + b_lm_noff;
                asm volatile(
                    "ldmatrix.sync.aligned.m8n8.x4.trans.shared.b16 {%0,%1,%2,%3}, [%4];"
                    : "=r"(bf[ni][0]), "=r"(bf[ni][1]),
                      "=r"(bf[ni + 1][0]), "=r"(bf[ni + 1][1])
                    : "r"(addr));
            }
            #pragma unroll
            for (int mi = 0; mi < 4; mi++)
                #pragma unroll
                for (int ni = 0; ni < 4; ni++)
                    asm volatile(
                        "mma.sync.aligned.m16n8k16.row.col.f32.f16.f16.f32 "
                        "{%0,%1,%2,%3}, {%4,%5,%6,%7}, {%8,%9}, {%0,%1,%2,%3};"
                        : "+f"(acc[mi][ni][0]), "+f"(acc[mi][ni][1]),
                          "+f"(acc[mi][ni][2]), "+f"(acc[mi][ni][3])
                        : "r"(af[mi][0]), "r"(af[mi][1]),
                          "r"(af[mi][2]), "r"(af[mi][3]),
                          "r"(bf[ni][0]), "r"(bf[ni][1]));
        }
        if (c + 1 < NCH) {
            sts_b(c + 1);                  // opposite buffer; safe per barrier
            if (c + 2 < NCH) ldg_b(c + 2);
        }
    }
    __syncthreads();

    // ---- epilogue ----
    #pragma unroll
    for (int mi = 0; mi < 4; mi++) {
        #pragma unroll
        for (int half = 0; half < 2; half++) {
            int r  = wm + mi * 16 + qr + half * 8;
            int gm = m0 + r;
            if (gm >= cnt) continue;
            if (FIRST) {
                __half* rowp = g_act16 + (size_t)(off + gm) * I_ + n0;
                #pragma unroll
                for (int ni = 0; ni < 2; ni++) {
                    int nc = wn + ni * 8 + qk * 2;
                    float g0 = acc[mi][ni][half * 2 + 0];
                    float g1 = acc[mi][ni][half * 2 + 1];
                    float u0 = acc[mi][ni + 2][half * 2 + 0];
                    float u1 = acc[mi][ni + 2][half * 2 + 1];
                    float v0 = u0 * (g0 / (1.f + __expf(-g0)));
                    float v1 = u1 * (g1 / (1.f + __expf(-g1)));
                    *(__half2*)(rowp + nc) = __floats2half2_rn(v0, v1);
                }
            } else {
                float w = g_w[off + gm];
                __half* rowp = g_dout16 + (size_t)(off + gm) * H_ + n0;
                #pragma unroll
                for (int ni = 0; ni < 4; ni++) {
                    int nc = wn + ni * 8 + qk * 2;
                    *(__half2*)(rowp + nc) =
                        __floats2half2_rn(acc[mi][ni][half * 2 + 0] * w,
                                          acc[mi][ni][half * 2 + 1] * w);
                }
            }
        }
    }
}

// ---------------- combine: fp16 dout -> fp32 out --------------------------------
__global__ void combine_kernel(float4* __restrict__ out) {
    int idx = blockIdx.x * blockDim.x + threadIdx.x;
    if (idx >= T_ * H_ / 4) return;
    int t  = idx >> 9;
    int h4 = idx & 511;
    float4 s = make_float4(0.f, 0.f, 0.f, 0.f);
    #pragma unroll
    for (int k = 0; k < 4; k++) {
        int pos = g_inv[4 * t + k];
        if (pos >= 0) {
            const __half2* p = (const __half2*)(g_dout16 + (size_t)pos * H_ + h4 * 4);
            float2 a = __half22float2(p[0]);
            float2 b = __half22float2(p[1]);
            s.x += a.x; s.y += a.y; s.z += b.x; s.w += b.y;
        }
    }
    out[idx] = s;
}

// ---------------- launch --------------------------------------------------------
extern "C" void kernel_launch(void* const* d_in, const int* in_sizes, int n_in,
                              void* d_out, int out_size) {
    const float* hs  = (const float*)d_in[0];
    const float* rw  = (const float*)d_in[1];
    const int*   ri  = (const int*)d_in[2];
    const float* gup = (const float*)d_in[4];
    const float* dn  = (const float*)d_in[5];
    float* out = (float*)d_out;

    cudaFuncSetAttribute((const void*)moe_gemm<2048, true>,
                         cudaFuncAttributeMaxDynamicSharedMemorySize, SMEM_BYTES);
    cudaFuncSetAttribute((const void*)moe_gemm<768, false>,
                         cudaFuncAttributeMaxDynamicSharedMemorySize, SMEM_BYTES);

    __half2* hs16; cudaGetSymbolAddress((void**)&hs16, g_hs16);
    const __half* hs16c = (const __half*)hs16;

    route_kernel<<<1, 256>>>(ri, rw);
    cvt_kernel<<<1024, 256>>>((const float4*)hs, hs16, T_ * H_ / 4);

    // x = m-tile (fastest), y = n-tile, z = expert
    moe_gemm<2048, true><<<dim3(8, 12, E_), 256, SMEM_BYTES>>>(hs16c, gup);
    moe_gemm<768, false><<<dim3(8, 16, E_), 256, SMEM_BYTES>>>(nullptr, dn);

    combine_kernel<<<(T_ * H_ / 4 + 255) / 256, 256>>>((float4*)out);
}

// round 17
// speedup vs baseline: 1.1055x; 1.0550x over previous
#include <cuda_runtime.h>
#include <cuda_fp16.h>
#include <cstdint>

static constexpr int E_   = 32;
static constexpr int H_   = 2048;
static constexpr int I_   = 768;
static constexpr int T_   = 2048;
static constexpr int MAXA = 8192;

// ---------------- scratch ----------------------------------------------------
__device__ int   g_counts[E_];
__device__ int   g_offsets[E_];
__device__ int   g_total;
__device__ int   g_tok[MAXA];
__device__ float g_w[MAXA];
__device__ int   g_inv[T_ * 4];
__device__ __align__(16) __half g_hs16[(size_t)T_ * H_];
__device__ __align__(16) __half g_act16[(size_t)MAXA * I_];
__device__ __align__(16) __half g_dout16[(size_t)MAXA * H_];

__device__ __forceinline__ uint32_t smem_u32(const void* p) {
    uint32_t a;
    asm("{ .reg .u64 t; cvta.to.shared.u64 t, %1; cvt.u32.u64 %0, t; }" : "=r"(a) : "l"(p));
    return a;
}
__device__ __forceinline__ void cpa16(uint32_t dst, const void* src) {
    asm volatile("cp.async.cg.shared.global [%0], [%1], 16;" :: "r"(dst), "l"(src));
}
__device__ __forceinline__ uint32_t pk2(float a, float b) {
    __half2 h = __floats2half2_rn(a, b);
    return *reinterpret_cast<uint32_t*>(&h);
}

// ---------------- fp32 -> fp16 streaming convert (hidden states only) ----------
__global__ void cvt_kernel(const float4* __restrict__ in, __half2* __restrict__ out, int n4) {
    for (int i = blockIdx.x * blockDim.x + threadIdx.x; i < n4;
         i += gridDim.x * blockDim.x) {
        float4 v = in[i];
        out[2 * i]     = __floats2half2_rn(v.x, v.y);
        out[2 * i + 1] = __floats2half2_rn(v.z, v.w);
    }
}

// ---------------- routing (known-good) ------------------------------------------
__global__ void route_kernel(const int* __restrict__ ridx,
                             const float* __restrict__ rw) {
    __shared__ int s_cnt[E_], s_cur[E_], s_off[E_];
    int tid = threadIdx.x;
    if (tid < E_) { s_cnt[tid] = 0; s_cur[tid] = 0; }
    __syncthreads();
    for (int t = tid; t < T_; t += blockDim.x) {
        int e0 = ridx[4*t], e1 = ridx[4*t+1], e2 = ridx[4*t+2], e3 = ridx[4*t+3];
        if (e0 != e1 && e0 != e2 && e0 != e3) atomicAdd(&s_cnt[e0], 1);
        if (e1 != e2 && e1 != e3)             atomicAdd(&s_cnt[e1], 1);
        if (e2 != e3)                          atomicAdd(&s_cnt[e2], 1);
        atomicAdd(&s_cnt[e3], 1);
    }
    __syncthreads();
    if (tid == 0) {
        int acc = 0;
        for (int e = 0; e < E_; e++) {
            s_off[e] = acc; g_offsets[e] = acc; g_counts[e] = s_cnt[e];
            acc += s_cnt[e];
        }
        g_total = acc;
    }
    __syncthreads();
    for (int t = tid; t < T_; t += blockDim.x) {
        int ee[4]; float ww[4];
        #pragma unroll
        for (int k = 0; k < 4; k++) { ee[k] = ridx[4*t+k]; ww[k] = rw[4*t+k]; }
        #pragma unroll
        for (int k = 0; k < 4; k++) {
            bool keep = true;
            #pragma unroll
            for (int j = k + 1; j < 4; j++) if (ee[j] == ee[k]) keep = false;
            int pos = -1;
            if (keep) {
                pos = s_off[ee[k]] + atomicAdd(&s_cur[ee[k]], 1);
                g_tok[pos] = t; g_w[pos] = ww[k];
            }
            g_inv[4*t + k] = pos;
        }
    }
}

// ---------------- fp16 grouped GEMM, fp32 B converted in-kernel (R13 core) -----
// 128x256 tile, 8 warps 64x64, k-chunk 32. A: cp.async fp16 4-stage.
// B: LDG fp32 -> cvt -> STS fp16, double-buffered.
// Restructure vs R13: sts_b/ldg_b/cp_a issued BEFORE the MMA loop (under MMA
// shadow) instead of after it; legal because the chunk-top barrier already
// proves buffer (c+1)&1 is drained.
static constexpr int A_PITCH = 80;
static constexpr int A_STG   = 128 * A_PITCH;        // 10240
static constexpr int A_TOTAL = 4 * A_STG;            // 40960
static constexpr int B_PITCH = 528;
static constexpr int B_BUF   = 32 * B_PITCH;         // 16896
static constexpr int SMEM_BYTES = A_TOTAL + 2 * B_BUF;  // 74752

template<int KDIM, bool FIRST>
__global__ void __launch_bounds__(256, 1)
moe_gemm(const __half* __restrict__ Ain, const float* __restrict__ Bfp32) {
    constexpr int NCH    = KDIM / 32;
    constexpr int LDB    = FIRST ? 1536 : 2048;
    constexpr int ROWSPE = FIRST ? 2048 : 768;
    constexpr int NOUT   = FIRST ? 128 : 256;

    extern __shared__ uint8_t smraw[];
    const int e   = blockIdx.z;
    const int cnt = g_counts[e];
    const int m0  = blockIdx.x * 128;   // m fastest
    if (m0 >= cnt) return;
    const int off = g_offsets[e];
    const int n0  = blockIdx.y * NOUT;
    const int tid = threadIdx.x;
    const int wid = tid >> 5, lane = tid & 31;
    const uint32_t sbase = smem_u32(smraw);

    // ---- A staging: row = tid>>1 (0..127), seg = tid&1 (32 B each) ----
    const int a_r = tid >> 1;
    const int a_s = tid & 1;
    int gmA = m0 + a_r;
    int rrA = (gmA < cnt) ? gmA : 0;
    const __half* aSrc = (FIRST ? Ain + (size_t)g_tok[off + rrA] * KDIM
                                : g_act16 + (size_t)(off + rrA) * KDIM) + a_s * 16;
    const uint32_t aDst = sbase + (uint32_t)(a_r * A_PITCH + a_s * 32);

    // ---- B staging: row = tid>>3 (0..31), seg s = tid&7 ----
    const int b_r = tid >> 3;
    const int b_s = tid & 7;
    const float* bColBase[4];
    #pragma unroll
    for (int j = 0; j < 4; j++) {
        int c8 = 8 * b_s + 64 * j;
        int gc = FIRST ? (c8 < 128 ? n0 + c8 : 768 + n0 + (c8 - 128))
                       : n0 + c8;
        bColBase[j] = Bfp32 + ((size_t)e * ROWSPE + b_r) * LDB + gc;
    }
    const uint32_t bDstBase = sbase + A_TOTAL + (uint32_t)(b_r * B_PITCH + b_s * 16);

    float4 breg[8];
    auto ldg_b = [&](int c) {
        const size_t roff = (size_t)c * 32 * LDB;
        #pragma unroll
        for (int j = 0; j < 4; j++) {
            breg[2 * j]     = *(const float4*)(bColBase[j] + roff);
            breg[2 * j + 1] = *(const float4*)(bColBase[j] + roff + 4);
        }
    };
    auto sts_b = [&](int c) {
        uint32_t dst = bDstBase + (uint32_t)(c & 1) * B_BUF;
        #pragma unroll
        for (int j = 0; j < 4; j++) {
            uint32_t h0 = pk2(breg[2*j].x,   breg[2*j].y);
            uint32_t h1 = pk2(breg[2*j].z,   breg[2*j].w);
            uint32_t h2 = pk2(breg[2*j+1].x, breg[2*j+1].y);
            uint32_t h3 = pk2(breg[2*j+1].z, breg[2*j+1].w);
            asm volatile("st.shared.v4.b32 [%0], {%1,%2,%3,%4};"
                         :: "r"(dst + (uint32_t)(j * 128)),
                            "r"(h0), "r"(h1), "r"(h2), "r"(h3) : "memory");
        }
    };
    auto cp_a = [&](int c) {
        const uint32_t so = (uint32_t)(c & 3) * A_STG;
        const __half* src = aSrc + (size_t)c * 32;
        cpa16(aDst + so, src);
        cpa16(aDst + so + 16, src + 8);
        asm volatile("cp.async.commit_group;" ::: "memory");
    };

    float acc[4][8][4];
    #pragma unroll
    for (int i = 0; i < 4; i++)
        #pragma unroll
        for (int j = 0; j < 8; j++)
            #pragma unroll
            for (int k = 0; k < 4; k++) acc[i][j][k] = 0.f;

    const int wm = (wid >> 2) * 64;
    const int wn = (wid & 3) * (FIRST ? 32 : 64);
    const int qr = lane >> 2;
    const int qk = lane & 3;

    const uint32_t a_lm_off = (uint32_t)((wm + (lane & 15)) * A_PITCH + (lane >> 4) * 16);
    const uint32_t b_lm_krow = (uint32_t)((lane & 7) + ((lane >> 3) & 1) * 8);
    const uint32_t b_lm_noff = (uint32_t)((lane >> 4) * 8 * 2);

    // ---- prologue ----
    ldg_b(0);
    cp_a(0); cp_a(1); cp_a(2);
    sts_b(0);
    ldg_b(1);

    for (int c = 0; c < NCH; c++) {
        int rem = NCH - 1 - c;
        if (rem >= 2)      asm volatile("cp.async.wait_group 2;" ::: "memory");
        else if (rem == 1) asm volatile("cp.async.wait_group 1;" ::: "memory");
        else               asm volatile("cp.async.wait_group 0;" ::: "memory");
        __syncthreads();

        // memory work first, under the MMA shadow:
        // barrier above proves buffer (c+1)&1 was drained by chunk c-1 readers
        if (c + 1 < NCH) sts_b(c + 1);
        if (c + 2 < NCH) ldg_b(c + 2);
        if (c + 3 < NCH) cp_a(c + 3);

        const uint32_t sA = sbase + (uint32_t)(c & 3) * A_STG;
        const uint32_t sB = sbase + A_TOTAL + (uint32_t)(c & 1) * B_BUF;
        #pragma unroll
        for (int kk = 0; kk < 32; kk += 16) {
            uint32_t af[4][4], bf[8][2];
            #pragma unroll
            for (int mi = 0; mi < 4; mi++) {
                uint32_t addr = sA + a_lm_off + (uint32_t)(mi * 16 * A_PITCH + kk * 2);
                asm volatile(
                    "ldmatrix.sync.aligned.m8n8.x4.shared.b16 {%0,%1,%2,%3}, [%4];"
                    : "=r"(af[mi][0]), "=r"(af[mi][1]),
                      "=r"(af[mi][2]), "=r"(af[mi][3])
                    : "r"(addr));
            }
            #pragma unroll
            for (int nip = 0; nip < 4; nip++) {
                int ni = 2 * nip;
                int nb = FIRST ? (ni < 4 ? wn + ni * 8 : 128 + wn + (ni - 4) * 8)
                               : wn + ni * 8;
                uint32_t addr = sB + (kk + b_lm_krow) * B_PITCH
                                   + (uint32_t)(nb * 2) + b_lm_noff;
                asm volatile(
                    "ldmatrix.sync.aligned.m8n8.x4.trans.shared.b16 {%0,%1,%2,%3}, [%4];"
                    : "=r"(bf[ni][0]), "=r"(bf[ni][1]),
                      "=r"(bf[ni + 1][0]), "=r"(bf[ni + 1][1])
                    : "r"(addr));
            }
            #pragma unroll
            for (int mi = 0; mi < 4; mi++)
                #pragma unroll
                for (int ni = 0; ni < 8; ni++)
                    asm volatile(
                        "mma.sync.aligned.m16n8k16.row.col.f32.f16.f16.f32 "
                        "{%0,%1,%2,%3}, {%4,%5,%6,%7}, {%8,%9}, {%0,%1,%2,%3};"
                        : "+f"(acc[mi][ni][0]), "+f"(acc[mi][ni][1]),
                          "+f"(acc[mi][ni][2]), "+f"(acc[mi][ni][3])
                        : "r"(af[mi][0]), "r"(af[mi][1]),
                          "r"(af[mi][2]), "r"(af[mi][3]),
                          "r"(bf[ni][0]), "r"(bf[ni][1]));
        }
    }
    __syncthreads();

    // ---- epilogue ----
    #pragma unroll
    for (int mi = 0; mi < 4; mi++) {
        #pragma unroll
        for (int half = 0; half < 2; half++) {
            int r  = wm + mi * 16 + qr + half * 8;
            int gm = m0 + r;
            if (gm >= cnt) continue;
            if (FIRST) {
                __half* rowp = g_act16 + (size_t)(off + gm) * I_ + n0;
                #pragma unroll
                for (int ni = 0; ni < 4; ni++) {
                    int nc = wn + ni * 8 + qk * 2;
                    float g0 = acc[mi][ni][half * 2 + 0];
                    float g1 = acc[mi][ni][half * 2 + 1];
                    float u0 = acc[mi][ni + 4][half * 2 + 0];
                    float u1 = acc[mi][ni + 4][half * 2 + 1];
                    float v0 = u0 * (g0 / (1.f + __expf(-g0)));
                    float v1 = u1 * (g1 / (1.f + __expf(-g1)));
                    *(__half2*)(rowp + nc) = __floats2half2_rn(v0, v1);
                }
            } else {
                float w = g_w[off + gm];
                __half* rowp = g_dout16 + (size_t)(off + gm) * H_ + n0;
                #pragma unroll
                for (int ni = 0; ni < 8; ni++) {
                    int nc = wn + ni * 8 + qk * 2;
                    *(__half2*)(rowp + nc) =
                        __floats2half2_rn(acc[mi][ni][half * 2 + 0] * w,
                                          acc[mi][ni][half * 2 + 1] * w);
                }
            }
        }
    }
}

// ---------------- combine: fp16 dout -> fp32 out --------------------------------
__global__ void combine_kernel(float4* __restrict__ out) {
    int idx = blockIdx.x * blockDim.x + threadIdx.x;
    if (idx >= T_ * H_ / 4) return;
    int t  = idx >> 9;
    int h4 = idx & 511;
    float4 s = make_float4(0.f, 0.f, 0.f, 0.f);
    #pragma unroll
    for (int k = 0; k < 4; k++) {
        int pos = g_inv[4 * t + k];
        if (pos >= 0) {
            const __half2* p = (const __half2*)(g_dout16 + (size_t)pos * H_ + h4 * 4);
            float2 a = __half22float2(p[0]);
            float2 b = __half22float2(p[1]);
            s.x += a.x; s.y += a.y; s.z += b.x; s.w += b.y;
        }
    }
    out[idx] = s;
}

// ---------------- launch --------------------------------------------------------
extern "C" void kernel_launch(void* const* d_in, const int* in_sizes, int n_in,
                              void* d_out, int out_size) {
    const float* hs  = (const float*)d_in[0];
    const float* rw  = (const float*)d_in[1];
    const int*   ri  = (const int*)d_in[2];
    const float* gup = (const float*)d_in[4];
    const float* dn  = (const float*)d_in[5];
    float* out = (float*)d_out;

    cudaFuncSetAttribute((const void*)moe_gemm<2048, true>,
                         cudaFuncAttributeMaxDynamicSharedMemorySize, SMEM_BYTES);
    cudaFuncSetAttribute((const void*)moe_gemm<768, false>,
                         cudaFuncAttributeMaxDynamicSharedMemorySize, SMEM_BYTES);

    __half2* hs16; cudaGetSymbolAddress((void**)&hs16, g_hs16);
    const __half* hs16c = (const __half*)hs16;

    route_kernel<<<1, 256>>>(ri, rw);
    cvt_kernel<<<1024, 256>>>((const float4*)hs, hs16, T_ * H_ / 4);

    // x = m-tile (fastest), y = n-tile, z = expert
    moe_gemm<2048, true><<<dim3(8, 6, E_), 256, SMEM_BYTES>>>(hs16c, gup);
    moe_gemm<768, false><<<dim3(8, 8, E_), 256, SMEM_BYTES>>>(nullptr, dn);

    combine_kernel<<<(T_ * H_ / 4 + 255) / 256, 256>>>((float4*)out);
}